// round 4
// baseline (speedup 1.0000x reference)
#include <cuda_runtime.h>
#include <math.h>

namespace {
constexpr int Bsz  = 8;
constexpr int Lsz  = 1024;
constexpr int Hsz  = 8;
constexpr int Esz  = 64;
constexpr int HIST = 512;
constexpr float SCALE = 0.125f;     // 1/sqrt(64)
constexpr int TILE = 64;
constexpr int STRP = 68;            // Ps stride (floats), 16B aligned
// Qs(64x64 swz) + Ks(64x64 swz) + Vt(64x64 swz, transposed) + Ps(64x68)
constexpr int SMEM_BYTES = (3 * 64 * 64 + 64 * STRP) * 4;
}

// ---- packed f32x2 helpers (SASS FFMA2 path; ptxas won't auto-fuse) ----
using u64 = unsigned long long;
__device__ __forceinline__ u64 ffma2(u64 a, u64 b, u64 c) {
    u64 d;
    asm("fma.rn.f32x2 %0, %1, %2, %3;" : "=l"(d) : "l"(a), "l"(b), "l"(c));
    return d;
}
__device__ __forceinline__ u64 mul2(u64 a, u64 b) {
    u64 d;
    asm("mul.rn.f32x2 %0, %1, %2;" : "=l"(d) : "l"(a), "l"(b));
    return d;
}
__device__ __forceinline__ u64 dup2(float x) {
    u64 d;
    asm("mov.b64 %0, {%1, %1};" : "=l"(d) : "f"(x));
    return d;
}
__device__ __forceinline__ float2 unpack2(u64 v) {
    float2 r;
    asm("mov.b64 {%0, %1}, %2;" : "=f"(r.x), "=f"(r.y) : "l"(v));
    return r;
}

// float offset of logical 16B-chunk c within swizzled row (row stride 64 floats)
__device__ __forceinline__ int swz(int row, int c) {
    return row * 64 + (((c) ^ ((row >> 2) & 15)) << 2);
}
// float offset of scalar logical element k within swizzled row
__device__ __forceinline__ int swz_s(int row, int k) {
    return row * 64 + ((((k >> 2)) ^ ((row >> 2) & 15)) << 2) + (k & 3);
}

__global__ __launch_bounds__(256, 2)
void fftcc_attn_kernel(const float* __restrict__ Q,  const float* __restrict__ K,
                       const float* __restrict__ V,  const float* __restrict__ QD,
                       const float* __restrict__ KD, const float* __restrict__ VD,
                       float* __restrict__ Out)
{
    extern __shared__ float sm[];
    float* Qs = sm;                       // [64 row][64 e], swizzled
    float* Ks = Qs + 64 * 64;             // [64 col][64 e], swizzled
    float* Vt = Ks + 64 * 64;             // [64 e][64 s], swizzled (V transposed)
    float* Ps = Vt + 64 * 64;             // [64 row][STRP s], plain

    const int bh = blockIdx.y;
    const int b  = bh >> 3;
    const int h  = bh & 7;
    const int m0  = (int)(gridDim.x - 1 - blockIdx.x) * TILE;  // heaviest first
    const int tid = threadIdx.x;
    const int ty  = tid >> 4;             // 0..15  -> rows 4ty..4ty+3
    const int tx  = tid & 15;             // 0..15  -> cols 4tx..4tx+3
    const int rs  = Hsz * Esz;            // 512
    const int base = (b * Lsz * Hsz + h) * Esz;

    // ---- Load Q tile (q_eff), coalesced, swizzled store ----
    {
        const int r0 = tid >> 4;
        const int ce = tid & 15;
        #pragma unroll
        for (int it = 0; it < 4; ++it) {
            const int r = r0 + it * 16;
            const int l = m0 + r;
            const float* src = (l < HIST) ? Q : QD;
            const float4 val = *reinterpret_cast<const float4*>(src + base + l * rs + (ce << 2));
            *reinterpret_cast<float4*>(Qs + swz(r, ce)) = val;
        }
    }
    __syncthreads();

    // ---- Diagonal replacement scores dS[i] = dot(q_eff[l], keys_drawn[l]) ----
    const bool has_diag_repl = (m0 >= HIST);
    float dS[4] = {0.f, 0.f, 0.f, 0.f};
    if (has_diag_repl && tx == ty) {
        #pragma unroll
        for (int i = 0; i < 4; ++i) {
            const int r = 4 * ty + i;
            const int l = m0 + r;
            const float* kr = KD + base + l * rs;
            float acc = 0.f;
            #pragma unroll
            for (int ce = 0; ce < 16; ++ce) {
                const float4 qv = *reinterpret_cast<const float4*>(Qs + swz(r, ce));
                const float4 kv = *reinterpret_cast<const float4*>(kr + (ce << 2));
                acc += qv.x * kv.x + qv.y * kv.y + qv.z * kv.z + qv.w * kv.w;
            }
            dS[i] = acc;
        }
    }

    u64 Op[4][4];                       // O[i][j] packed partial sums over s
    float mrow[4], lsum[4];
    #pragma unroll
    for (int i = 0; i < 4; ++i) {
        mrow[i] = -INFINITY; lsum[i] = 0.f;
        #pragma unroll
        for (int j = 0; j < 4; ++j) Op[i][j] = 0ull;
    }

    const int ntiles = (m0 >> 6) + 1;
    for (int t = 0; t < ntiles; ++t) {
        const int n0 = t << 6;
        const bool diag = (n0 == m0);

        __syncthreads();   // previous iteration's readers done with Ks/Vt
        // ---- Load K (row-major swizzled) ----
        {
            const int r0 = tid >> 4;
            const int ce = tid & 15;
            #pragma unroll
            for (int it = 0; it < 4; ++it) {
                const int r = r0 + it * 16;
                const float4 kv = *reinterpret_cast<const float4*>(K + base + (n0 + r) * rs + (ce << 2));
                *reinterpret_cast<float4*>(Ks + swz(r, ce)) = kv;
            }
        }
        // ---- Load V transposed: Vt[e][s], conflict-free scalar STS (s = lane) ----
        {
            const int r  = tid & 63;       // s index, consecutive across warp
            const int q4 = tid >> 6;       // e-chunk phase
            #pragma unroll
            for (int it = 0; it < 4; ++it) {
                const int c = q4 + 4 * it;  // e-chunk 0..15
                const float4 vv = *reinterpret_cast<const float4*>(V + base + (n0 + r) * rs + (c << 2));
                Vt[swz_s(4 * c + 0, r)] = vv.x;
                Vt[swz_s(4 * c + 1, r)] = vv.y;
                Vt[swz_s(4 * c + 2, r)] = vv.z;
                Vt[swz_s(4 * c + 3, r)] = vv.w;
            }
        }
        __syncthreads();

        // ---- S = Q @ K^T : packed over e (FFMA2) ----
        u64 Sp[4][4];
        #pragma unroll
        for (int i = 0; i < 4; ++i)
            #pragma unroll
            for (int j = 0; j < 4; ++j) Sp[i][j] = 0ull;

        #pragma unroll 4
        for (int e4 = 0; e4 < 16; ++e4) {
            ulonglong2 qv[4], kv[4];
            #pragma unroll
            for (int i = 0; i < 4; ++i)
                qv[i] = *reinterpret_cast<const ulonglong2*>(Qs + swz(4 * ty + i, e4));
            #pragma unroll
            for (int j = 0; j < 4; ++j)
                kv[j] = *reinterpret_cast<const ulonglong2*>(Ks + swz(4 * tx + j, e4));
            #pragma unroll
            for (int i = 0; i < 4; ++i)
                #pragma unroll
                for (int j = 0; j < 4; ++j) {
                    Sp[i][j] = ffma2(qv[i].x, kv[j].x, Sp[i][j]);
                    Sp[i][j] = ffma2(qv[i].y, kv[j].y, Sp[i][j]);
                }
        }

        // ---- unpack, diagonal substitution, scale, causal mask, softmax ----
        #pragma unroll
        for (int i = 0; i < 4; ++i) {
            float S[4];
            #pragma unroll
            for (int j = 0; j < 4; ++j) {
                const float2 p = unpack2(Sp[i][j]);
                S[j] = p.x + p.y;
            }
            if (diag && has_diag_repl && tx == ty) S[i] = dS[i];
            #pragma unroll
            for (int j = 0; j < 4; ++j) S[j] *= SCALE;
            if (diag) {
                #pragma unroll
                for (int j = 0; j < 4; ++j)
                    if ((4 * tx + j) > (4 * ty + i)) S[j] = -INFINITY;
            }

            float mx = fmaxf(fmaxf(S[0], S[1]), fmaxf(S[2], S[3]));
            #pragma unroll
            for (int o = 8; o > 0; o >>= 1)
                mx = fmaxf(mx, __shfl_xor_sync(0xffffffffu, mx, o));
            const float nm   = fmaxf(mrow[i], mx);
            const float corr = __expf(mrow[i] - nm);   // first tile: exp(-inf)=0
            mrow[i] = nm;
            float rsum = 0.f;
            #pragma unroll
            for (int j = 0; j < 4; ++j) {
                S[j] = __expf(S[j] - nm);
                rsum += S[j];
            }
            #pragma unroll
            for (int o = 8; o > 0; o >>= 1)
                rsum += __shfl_xor_sync(0xffffffffu, rsum, o);
            lsum[i] = lsum[i] * corr + rsum;

            const u64 cd = dup2(corr);
            #pragma unroll
            for (int j = 0; j < 4; ++j) Op[i][j] = mul2(Op[i][j], cd);

            *reinterpret_cast<float4*>(Ps + (4 * ty + i) * STRP + 4 * tx)
                = make_float4(S[0], S[1], S[2], S[3]);
        }
        // P rows 4ty+i produced & consumed within this warp
        __syncwarp();

        // ---- O += P @ V : packed over s (FFMA2) ----
        #pragma unroll 4
        for (int s4 = 0; s4 < 16; ++s4) {
            ulonglong2 pv[4], vv[4];
            #pragma unroll
            for (int i = 0; i < 4; ++i)
                pv[i] = *reinterpret_cast<const ulonglong2*>(Ps + (4 * ty + i) * STRP + (s4 << 2));
            #pragma unroll
            for (int j = 0; j < 4; ++j)
                vv[j] = *reinterpret_cast<const ulonglong2*>(Vt + swz(4 * tx + j, s4));
            #pragma unroll
            for (int i = 0; i < 4; ++i)
                #pragma unroll
                for (int j = 0; j < 4; ++j) {
                    Op[i][j] = ffma2(pv[i].x, vv[j].x, Op[i][j]);
                    Op[i][j] = ffma2(pv[i].y, vv[j].y, Op[i][j]);
                }
        }
    }

    // ---- epilogue: unpack O, diagonal value substitution, normalize, store ----
    // Diag tile was the LAST tile, so Ps/Vt still hold it.
    #pragma unroll
    for (int i = 0; i < 4; ++i) {
        const int r = 4 * ty + i;
        const int l = m0 + r;
        float O[4];
        #pragma unroll
        for (int j = 0; j < 4; ++j) {
            const float2 p = unpack2(Op[i][j]);
            O[j] = p.x + p.y;
        }
        if (has_diag_repl) {
            const float pd = Ps[r * STRP + r];
            const float4 vdr = *reinterpret_cast<const float4*>(VD + base + l * rs + 4 * tx);
            O[0] += pd * (vdr.x - Vt[swz_s(4 * tx + 0, r)]);
            O[1] += pd * (vdr.y - Vt[swz_s(4 * tx + 1, r)]);
            O[2] += pd * (vdr.z - Vt[swz_s(4 * tx + 2, r)]);
            O[3] += pd * (vdr.w - Vt[swz_s(4 * tx + 3, r)]);
        }
        const float inv = 1.0f / lsum[i];
        *reinterpret_cast<float4*>(Out + base + l * rs + 4 * tx)
            = make_float4(O[0] * inv, O[1] * inv, O[2] * inv, O[3] * inv);
    }
}

extern "C" void kernel_launch(void* const* d_in, const int* in_sizes, int n_in,
                              void* d_out, int out_size)
{
    const float* Q  = (const float*)d_in[0];
    const float* K  = (const float*)d_in[1];
    const float* V  = (const float*)d_in[2];
    const float* QD = (const float*)d_in[3];
    const float* KD = (const float*)d_in[4];
    const float* VD = (const float*)d_in[5];
    float* Out = (float*)d_out;

    cudaFuncSetAttribute(fftcc_attn_kernel,
                         cudaFuncAttributeMaxDynamicSharedMemorySize, SMEM_BYTES);
    dim3 grid(Lsz / TILE, Bsz * Hsz);   // (16, 64)
    fftcc_attn_kernel<<<grid, 256, SMEM_BYTES>>>(Q, K, V, QD, KD, VD, Out);
}

// round 5
// speedup vs baseline: 4.6414x; 4.6414x over previous
#include <cuda_runtime.h>
#include <math.h>

namespace {
constexpr int Bsz  = 8;
constexpr int Lsz  = 1024;
constexpr int Hsz  = 8;
constexpr int Esz  = 64;
constexpr int HIST = 512;
constexpr float SCALE = 0.125f;   // 1/sqrt(64)
constexpr int BM = 128;           // q rows per block
constexpr int BN = 64;            // key tile
constexpr int SK = 68;            // K / P / Q smem stride (floats) — conflict-free frag LDS
constexpr int SV = 72;            // V smem stride — conflict-free B-frag LDS
constexpr int SM_QP = BM * SK;    // Qs, reused as Ps
constexpr int SM_K  = BN * SK;
constexpr int SM_V  = BN * SV;
constexpr int SMEM_BYTES = (SM_QP + SM_K + SM_V + BM + BM) * 4;
}

__device__ __forceinline__ unsigned f2tf(float x) {
    unsigned u;
    asm("cvt.rna.tf32.f32 %0, %1;" : "=r"(u) : "f"(x));
    return u;
}
__device__ __forceinline__ float f2tf_f(float x) { return __uint_as_float(f2tf(x)); }

__device__ __forceinline__ void mma_tf32(float* d, const unsigned* a, unsigned b0, unsigned b1) {
    asm("mma.sync.aligned.m16n8k8.row.col.f32.tf32.tf32.f32 "
        "{%0,%1,%2,%3},{%4,%5,%6,%7},{%8,%9},{%0,%1,%2,%3};"
        : "+f"(d[0]), "+f"(d[1]), "+f"(d[2]), "+f"(d[3])
        : "r"(a[0]), "r"(a[1]), "r"(a[2]), "r"(a[3]), "r"(b0), "r"(b1));
}

__global__ __launch_bounds__(256, 1)
void fftcc_attn_kernel(const float* __restrict__ Q,  const float* __restrict__ K,
                       const float* __restrict__ V,  const float* __restrict__ QD,
                       const float* __restrict__ KD, const float* __restrict__ VD,
                       float* __restrict__ Out)
{
    extern __shared__ float smem[];
    float* Qs  = smem;                 // [BM][SK] tf32 Q; reused as Ps after frag extraction
    float* Ks  = Qs + SM_QP;           // [BN][SK] tf32 K tile
    float* Vs  = Ks + SM_K;            // [BN][SV] tf32 V tile
    float* dSs = Vs + SM_V;            // [BM] raw diag scores
    float* pdS = dSs + BM;             // [BM] diag probabilities (unnormalized)

    const int bh = blockIdx.y;
    const int b  = bh >> 3;
    const int h  = bh & 7;
    const int m0 = (int)(gridDim.x - 1 - blockIdx.x) * BM;   // heaviest first
    const int tid  = threadIdx.x;
    const int w    = tid >> 5;
    const int lane = tid & 31;
    const int rr   = lane >> 2;        // 0..7  (row in group)
    const int qi   = lane & 3;         // 0..3  (thread-in-group)
    const int rs   = Hsz * Esz;        // 512
    const int base = (b * Lsz * Hsz + h) * Esz;
    const bool has_diag = (m0 >= HIST);   // BM=128 divides HIST cleanly

    // ---- Load Q (q_eff) as tf32 into smem ----
    #pragma unroll
    for (int it = 0; it < 8; ++it) {
        const int idx = it * 256 + tid;          // 0..2047
        const int r  = idx >> 4;
        const int ce = idx & 15;
        const int l  = m0 + r;
        const float* src = (l < HIST) ? Q : QD;
        const float4 v = *reinterpret_cast<const float4*>(src + base + l * rs + (ce << 2));
        *reinterpret_cast<float4*>(Qs + r * SK + (ce << 2)) =
            make_float4(f2tf_f(v.x), f2tf_f(v.y), f2tf_f(v.z), f2tf_f(v.w));
    }
    // ---- Diagonal raw scores (full fp32) ----
    if (has_diag && tid < BM) {
        const int l = m0 + tid;                  // all rows >= HIST here
        const float* qr = QD + base + l * rs;
        const float* kr = KD + base + l * rs;
        float acc = 0.f;
        #pragma unroll
        for (int ce = 0; ce < 16; ++ce) {
            const float4 qv = *reinterpret_cast<const float4*>(qr + (ce << 2));
            const float4 kv = *reinterpret_cast<const float4*>(kr + (ce << 2));
            acc += qv.x * kv.x + qv.y * kv.y + qv.z * kv.z + qv.w * kv.w;
        }
        dSs[tid] = acc;
    }
    __syncthreads();

    // ---- Extract Q A-fragments (held for entire kernel) ----
    const int rowA = w * 16 + rr;                // this thread's first row (local)
    unsigned qa[8][4];
    #pragma unroll
    for (int k = 0; k < 8; ++k) {
        qa[k][0] = __float_as_uint(Qs[(rowA    ) * SK + k * 8 + qi    ]);
        qa[k][1] = __float_as_uint(Qs[(rowA + 8) * SK + k * 8 + qi    ]);
        qa[k][2] = __float_as_uint(Qs[(rowA    ) * SK + k * 8 + qi + 4]);
        qa[k][3] = __float_as_uint(Qs[(rowA + 8) * SK + k * 8 + qi + 4]);
    }

    float o[8][4];
    #pragma unroll
    for (int nf = 0; nf < 8; ++nf)
        #pragma unroll
        for (int c = 0; c < 4; ++c) o[nf][c] = 0.f;
    float mrow0 = -INFINITY, mrow1 = -INFINITY, lsum0 = 0.f, lsum1 = 0.f;

    float* Ps = Qs;                              // reuse Q smem region for P
    const int ntiles = (m0 >> 6) + 2;            // keys 0 .. m0+127

    for (int t = 0; t < ntiles; ++t) {
        const int n0 = t << 6;
        const bool crossing = (n0 >= m0);        // last two tiles: mask (+diag)

        __syncthreads();                         // prev readers done with Ks/Vs
        // ---- Load K, V tiles as tf32 ----
        #pragma unroll
        for (int it = 0; it < 4; ++it) {
            const int idx = it * 256 + tid;      // 0..1023
            const int r  = idx >> 4;
            const int ce = idx & 15;
            const int g = base + (n0 + r) * rs + (ce << 2);
            const float4 kv = *reinterpret_cast<const float4*>(K + g);
            const float4 vv = *reinterpret_cast<const float4*>(V + g);
            *reinterpret_cast<float4*>(Ks + r * SK + (ce << 2)) =
                make_float4(f2tf_f(kv.x), f2tf_f(kv.y), f2tf_f(kv.z), f2tf_f(kv.w));
            *reinterpret_cast<float4*>(Vs + r * SV + (ce << 2)) =
                make_float4(f2tf_f(vv.x), f2tf_f(vv.y), f2tf_f(vv.z), f2tf_f(vv.w));
        }
        __syncthreads();

        // ---- S = Q @ K^T  (tf32 mma) ----
        float s[8][4];
        #pragma unroll
        for (int nf = 0; nf < 8; ++nf) {
            #pragma unroll
            for (int c = 0; c < 4; ++c) s[nf][c] = 0.f;
            #pragma unroll
            for (int k = 0; k < 8; ++k) {
                const unsigned b0 = __float_as_uint(Ks[(nf * 8 + rr) * SK + k * 8 + qi    ]);
                const unsigned b1 = __float_as_uint(Ks[(nf * 8 + rr) * SK + k * 8 + qi + 4]);
                mma_tf32(s[nf], qa[k], b0, b1);
            }
        }

        const int l0 = m0 + w * 16 + rr;         // global rows of c0/c1 and c2/c3
        const int l1 = l0 + 8;

        // ---- diag substitution + causal mask (only crossing tiles) ----
        if (crossing) {
            #pragma unroll
            for (int nf = 0; nf < 8; ++nf) {
                const int col = n0 + nf * 8 + 2 * qi;
                if (has_diag) {
                    if (col     == l0) s[nf][0] = dSs[l0 - m0];
                    if (col + 1 == l0) s[nf][1] = dSs[l0 - m0];
                    if (col     == l1) s[nf][2] = dSs[l1 - m0];
                    if (col + 1 == l1) s[nf][3] = dSs[l1 - m0];
                }
                if (col     > l0) s[nf][0] = -INFINITY;
                if (col + 1 > l0) s[nf][1] = -INFINITY;
                if (col     > l1) s[nf][2] = -INFINITY;
                if (col + 1 > l1) s[nf][3] = -INFINITY;
            }
        }

        // ---- online softmax (rows warp-local; quad reduce over lanes qi) ----
        float mx0 = -INFINITY, mx1 = -INFINITY;
        #pragma unroll
        for (int nf = 0; nf < 8; ++nf) {
            #pragma unroll
            for (int c = 0; c < 4; ++c) s[nf][c] *= SCALE;
            mx0 = fmaxf(mx0, fmaxf(s[nf][0], s[nf][1]));
            mx1 = fmaxf(mx1, fmaxf(s[nf][2], s[nf][3]));
        }
        #pragma unroll
        for (int off = 1; off <= 2; off <<= 1) {
            mx0 = fmaxf(mx0, __shfl_xor_sync(0xffffffffu, mx0, off));
            mx1 = fmaxf(mx1, __shfl_xor_sync(0xffffffffu, mx1, off));
        }
        const float nm0 = fmaxf(mrow0, mx0);
        const float nm1 = fmaxf(mrow1, mx1);
        const float corr0 = __expf(mrow0 - nm0);     // first tile: exp(-inf)=0
        const float corr1 = __expf(mrow1 - nm1);
        mrow0 = nm0; mrow1 = nm1;

        float rs0 = 0.f, rs1 = 0.f;
        #pragma unroll
        for (int nf = 0; nf < 8; ++nf) {
            s[nf][0] = __expf(s[nf][0] - nm0);
            s[nf][1] = __expf(s[nf][1] - nm0);
            s[nf][2] = __expf(s[nf][2] - nm1);
            s[nf][3] = __expf(s[nf][3] - nm1);
            rs0 += s[nf][0] + s[nf][1];
            rs1 += s[nf][2] + s[nf][3];
        }
        #pragma unroll
        for (int off = 1; off <= 2; off <<= 1) {
            rs0 += __shfl_xor_sync(0xffffffffu, rs0, off);
            rs1 += __shfl_xor_sync(0xffffffffu, rs1, off);
        }
        lsum0 = lsum0 * corr0 + rs0;
        lsum1 = lsum1 * corr1 + rs1;
        #pragma unroll
        for (int nf = 0; nf < 8; ++nf) {
            o[nf][0] *= corr0; o[nf][1] *= corr0;
            o[nf][2] *= corr1; o[nf][3] *= corr1;
        }

        // ---- capture diag probabilities; store P (tf32) ----
        if (crossing && has_diag) {
            #pragma unroll
            for (int nf = 0; nf < 8; ++nf) {
                const int col = n0 + nf * 8 + 2 * qi;
                if (col     == l0) pdS[l0 - m0] = s[nf][0];
                if (col + 1 == l0) pdS[l0 - m0] = s[nf][1];
                if (col     == l1) pdS[l1 - m0] = s[nf][2];
                if (col + 1 == l1) pdS[l1 - m0] = s[nf][3];
            }
        }
        {
            const int r0l = w * 16 + rr;
            #pragma unroll
            for (int nf = 0; nf < 8; ++nf) {
                *reinterpret_cast<float2*>(Ps + (r0l    ) * SK + nf * 8 + 2 * qi) =
                    make_float2(f2tf_f(s[nf][0]), f2tf_f(s[nf][1]));
                *reinterpret_cast<float2*>(Ps + (r0l + 8) * SK + nf * 8 + 2 * qi) =
                    make_float2(f2tf_f(s[nf][2]), f2tf_f(s[nf][3]));
            }
        }
        __syncwarp();     // P rows are warp-private (produced & consumed by this warp)

        // ---- O += P @ V  (tf32 mma) ----
        #pragma unroll
        for (int k = 0; k < 8; ++k) {
            unsigned pa[4];
            pa[0] = __float_as_uint(Ps[(rowA    ) * SK + k * 8 + qi    ]);
            pa[1] = __float_as_uint(Ps[(rowA + 8) * SK + k * 8 + qi    ]);
            pa[2] = __float_as_uint(Ps[(rowA    ) * SK + k * 8 + qi + 4]);
            pa[3] = __float_as_uint(Ps[(rowA + 8) * SK + k * 8 + qi + 4]);
            #pragma unroll
            for (int nf = 0; nf < 8; ++nf) {
                const unsigned b0 = __float_as_uint(Vs[(k * 8 + qi    ) * SV + nf * 8 + rr]);
                const unsigned b1 = __float_as_uint(Vs[(k * 8 + qi + 4) * SV + nf * 8 + rr]);
                mma_tf32(o[nf], pa, b0, b1);
            }
        }
        __syncwarp();     // done reading Ps before next iteration overwrites
    }

    // ---- epilogue: diag value substitution, normalize, store ----
    __syncwarp();
    const int l0 = m0 + w * 16 + rr;
    const int l1 = l0 + 8;
    const float inv0 = 1.0f / lsum0;
    const float inv1 = 1.0f / lsum1;
    const float pd0 = has_diag ? pdS[l0 - m0] : 0.f;
    const float pd1 = has_diag ? pdS[l1 - m0] : 0.f;

    #pragma unroll
    for (int nf = 0; nf < 8; ++nf) {
        const int e = nf * 8 + 2 * qi;
        float v00 = o[nf][0], v01 = o[nf][1], v10 = o[nf][2], v11 = o[nf][3];
        if (has_diag) {
            const float2 vd0 = *reinterpret_cast<const float2*>(VD + base + l0 * rs + e);
            const float2 vo0 = *reinterpret_cast<const float2*>(V  + base + l0 * rs + e);
            const float2 vd1 = *reinterpret_cast<const float2*>(VD + base + l1 * rs + e);
            const float2 vo1 = *reinterpret_cast<const float2*>(V  + base + l1 * rs + e);
            v00 += pd0 * (vd0.x - vo0.x);
            v01 += pd0 * (vd0.y - vo0.y);
            v10 += pd1 * (vd1.x - vo1.x);
            v11 += pd1 * (vd1.y - vo1.y);
        }
        *reinterpret_cast<float2*>(Out + base + l0 * rs + e) = make_float2(v00 * inv0, v01 * inv0);
        *reinterpret_cast<float2*>(Out + base + l1 * rs + e) = make_float2(v10 * inv1, v11 * inv1);
    }
}

extern "C" void kernel_launch(void* const* d_in, const int* in_sizes, int n_in,
                              void* d_out, int out_size)
{
    const float* Q  = (const float*)d_in[0];
    const float* K  = (const float*)d_in[1];
    const float* V  = (const float*)d_in[2];
    const float* QD = (const float*)d_in[3];
    const float* KD = (const float*)d_in[4];
    const float* VD = (const float*)d_in[5];
    float* Out = (float*)d_out;

    cudaFuncSetAttribute(fftcc_attn_kernel,
                         cudaFuncAttributeMaxDynamicSharedMemorySize, SMEM_BYTES);
    dim3 grid(Lsz / BM, Bsz * Hsz);    // (8, 64)
    fftcc_attn_kernel<<<grid, 256, SMEM_BYTES>>>(Q, K, V, QD, KD, VD, Out);
}